// round 6
// baseline (speedup 1.0000x reference)
#include <cuda_runtime.h>

#define BB 65536
#define VV 4
#define BPB 8                         // batches per block
#define THREADS 128                   // 4 threads per (batch,view) task
#define NBLK (BB / BPB)               // 8192

// shared layout
#define KW4   0                       // f4 units: 8 batches x stride 25 (24 data + pad)
#define CAMF  800                     // floats: 8 x stride 49
#define KKF   1192                    // floats: 8 x stride 37
#define SMEM_FLOATS 1488
#define SMEM_BYTES (SMEM_FLOATS * 4)  // 5952

__device__ float g_partials[NBLK];
__device__ unsigned int g_ticket;

static __device__ __forceinline__ float warp_sum(float v) {
#pragma unroll
    for (int o = 16; o; o >>= 1) v += __shfl_xor_sync(0xFFFFFFFFu, v, o);
    return v;
}
// sum across the 4 threads of one task (lanes differing in bits 0,1)
static __device__ __forceinline__ float quad_sum(float v) {
    v += __shfl_xor_sync(0xFFFFFFFFu, v, 1);
    v += __shfl_xor_sync(0xFFFFFFFFu, v, 2);
    return v;
}

__global__ __launch_bounds__(THREADS, 6) void proj_loss(
    const float* __restrict__ Kmat,   // (B,V,3,3)
    const float* __restrict__ cam,    // (B,V,3,4)
    const float* __restrict__ kw,     // (B,J,3)
    const float* __restrict__ ik,     // (B,V,J,2)
    float* __restrict__ out)
{
    extern __shared__ float sm[];
    float4* sm4 = (float4*)sm;
    __shared__ float s_w[4];
    __shared__ int s_last;

    const int tid = threadIdx.x;
    const int b0 = blockIdx.x * BPB;

    // ---------------- staging: only kw/cam/K go through smem ----------------
    {   // kw: 8*24 = 192 f4
        const float4* g = (const float4*)(kw + (size_t)b0 * 96);
#pragma unroll
        for (int r = 0; r < 2; ++r) {
            int i = tid + r * 128;
            if (i < 192) {
                int b = i / 24, k = i - b * 24;
                sm4[KW4 + b * 25 + k] = __ldcs(&g[i]);
            }
        }
    }
    {   // cam: 8*12 = 96 f4 -> scalar scatter to odd-stride rows
        const float4* g = (const float4*)(cam + (size_t)b0 * 48);
        if (tid < 96) {
            int b = tid / 12, k = tid - b * 12;
            float4 val = __ldcs(&g[tid]);
            int base = CAMF + b * 49 + k * 4;
            sm[base] = val.x; sm[base + 1] = val.y;
            sm[base + 2] = val.z; sm[base + 3] = val.w;
        }
    }
    {   // K: 8*9 = 72 f4
        const float4* g = (const float4*)(Kmat + (size_t)b0 * 36);
        if (tid < 72) {
            int b = tid / 9, k = tid - b * 9;
            float4 val = __ldcs(&g[tid]);
            int base = KKF + b * 37 + k * 4;
            sm[base] = val.x; sm[base + 1] = val.y;
            sm[base + 2] = val.z; sm[base + 3] = val.w;
        }
    }

    // ----- ik: per-thread contiguous 64B, straight from gmem to registers -----
    // task (bl, v), quarter h -> joints 8h..8h+7
    const int h  = tid & 3;
    const int v  = (tid >> 2) & 3;
    const int bl = tid >> 4;
    float4 q[4];
    {
        const float4* g = (const float4*)(ik + (size_t)b0 * 256)
                        + ((bl * 4 + v) * 16 + 4 * h);
#pragma unroll
        for (int k = 0; k < 4; ++k) q[k] = __ldcs(&g[k]);
    }
    float ni2 = 0.f;
#pragma unroll
    for (int k = 0; k < 4; ++k) {
        ni2 = fmaf(q[k].x, q[k].x, fmaf(q[k].y, q[k].y, ni2));
        ni2 = fmaf(q[k].z, q[k].z, fmaf(q[k].w, q[k].w, ni2));
    }
    __syncthreads();

    // ---------------- camera / intrinsics (smem broadcast reads) -------------
    const float* cv = &sm[CAMF + bl * 49 + v * 12];
    const float R00=cv[0], R01=cv[1], R02=cv[2],  t0=cv[3];
    const float R10=cv[4], R11=cv[5], R12=cv[6],  t1=cv[7];
    const float R20=cv[8], R21=cv[9], R22=cv[10], t2=cv[11];
    const float* kp = &sm[KKF + bl * 37 + v * 9];
    const float K00=kp[0], K01=kp[1], c0=kp[2];
    const float K10=kp[3], K11=kp[4], c1=kp[5];

    // folded rows: ux = (A0.X + d0)*izb + c0
    const float A00 = fmaf(K00, R00, K01 * R10);
    const float A01 = fmaf(K00, R01, K01 * R11);
    const float A02 = fmaf(K00, R02, K01 * R12);
    const float d0  = fmaf(K00, t0,  K01 * t1);
    const float A10 = fmaf(K10, R00, K11 * R10);
    const float A11 = fmaf(K10, R01, K11 * R11);
    const float A12 = fmaf(K10, R02, K11 * R12);
    const float d1  = fmaf(K10, t0,  K11 * t1);

    // ------------- single pass over X: numerators + z partial -------------
    const int xb = KW4 + bl * 25 + 6 * h;   // this quarter's 6 f4 of X
    float2 uv[8];
    float Szp = 0.f;
#pragma unroll
    for (int g = 0; g < 2; ++g) {
        float4 p0 = sm4[xb + g * 3];
        float4 p1 = sm4[xb + g * 3 + 1];
        float4 p2 = sm4[xb + g * 3 + 2];
        float xs[4] = {p0.x, p0.w, p1.z, p2.y};
        float ys[4] = {p0.y, p1.x, p1.w, p2.z};
        float zs[4] = {p0.z, p1.y, p2.x, p2.w};
#pragma unroll
        for (int j = 0; j < 4; ++j) {
            int jj = g * 4 + j;
            uv[jj].x = fmaf(A00, xs[j], fmaf(A01, ys[j], fmaf(A02, zs[j], d0)));
            uv[jj].y = fmaf(A10, xs[j], fmaf(A11, ys[j], fmaf(A12, zs[j], d1)));
            Szp = fmaf(R20, xs[j], fmaf(R21, ys[j], fmaf(R22, zs[j], Szp)));
        }
    }
    const float zbar = quad_sum(Szp) * (1.0f / 32.0f) + t2;
    const float izb  = __fdividef(1.0f, zbar);

    // ------------- finish uv, accumulate norms (registers only) -------------
    float np2 = 0.f;
#pragma unroll
    for (int j = 0; j < 8; ++j) {
        float ux = fmaf(uv[j].x, izb, c0);
        float uy = fmaf(uv[j].y, izb, c1);
        uv[j] = make_float2(ux, uy);
        np2 = fmaf(ux, ux, fmaf(uy, uy, np2));
    }
    np2 = quad_sum(np2);
    ni2 = quad_sum(ni2);
    const float rp = rsqrtf(np2);
    const float ri = rsqrtf(ni2);

    float acc = 0.f;
#pragma unroll
    for (int k = 0; k < 4; ++k) {
        acc += fabsf(fmaf(uv[2*k].x,   rp, -q[k].x * ri))
             + fabsf(fmaf(uv[2*k].y,   rp, -q[k].y * ri))
             + fabsf(fmaf(uv[2*k+1].x, rp, -q[k].z * ri))
             + fabsf(fmaf(uv[2*k+1].y, rp, -q[k].w * ri));
    }

    // ---------------- block partial + last-block deterministic reduce --------
    acc = warp_sum(acc);
    if ((tid & 31) == 0) s_w[tid >> 5] = acc;
    __syncthreads();
    if (tid == 0) {
        float bsum = s_w[0] + s_w[1] + s_w[2] + s_w[3];
        __stcg(&g_partials[blockIdx.x], bsum);
        __threadfence();
        unsigned int t = atomicAdd(&g_ticket, 1u);
        s_last = (t == NBLK - 1u);
    }
    __syncthreads();

    if (s_last) {
        float a = 0.f;
#pragma unroll
        for (int i = 0; i < NBLK / THREADS; ++i)
            a += __ldcg(&g_partials[tid * (NBLK / THREADS) + i]);
        a = warp_sum(a);
        if ((tid & 31) == 0) s_w[tid >> 5] = a;
        __syncthreads();
        if (tid == 0) {
            float tot = s_w[0] + s_w[1] + s_w[2] + s_w[3];
            out[0] = tot * (1.0f / (64.0f * (float)BB * (float)VV));
            g_ticket = 0u;
        }
    }
}

extern "C" void kernel_launch(void* const* d_in, const int* in_sizes, int n_in,
                              void* d_out, int out_size)
{
    const float* Kmat = (const float*)d_in[0];  // (B,V,3,3)
    const float* cam  = (const float*)d_in[1];  // (B,V,3,4)
    const float* kw   = (const float*)d_in[2];  // (B,J,3)
    const float* ik   = (const float*)d_in[3];  // (B,V,J,2)
    float* out = (float*)d_out;

    cudaFuncSetAttribute(proj_loss, cudaFuncAttributeMaxDynamicSharedMemorySize, SMEM_BYTES);
    proj_loss<<<NBLK, THREADS, SMEM_BYTES>>>(Kmat, cam, kw, ik, out);
}

// round 7
// speedup vs baseline: 1.0066x; 1.0066x over previous
#include <cuda_runtime.h>

#define BB 65536
#define VV 4
#define BPB 8                         // batches per block
#define THREADS 128                   // 4 threads per (batch,view) task
#define NBLK (BB / BPB)               // 8192

// shared layout
#define KW4   0                       // f4: 8 batches x stride 25 (24 data + pad)
#define IK4   200                     // f4: transposed ik, 4 slots x stride 129
#define CAMF  2864                    // floats: 8 x stride 49
#define KKF   3256                    // floats: 8 x stride 37
#define SMEM_FLOATS 3552
#define SMEM_BYTES (SMEM_FLOATS * 4)  // 14208

__device__ float g_partials[NBLK];
__device__ unsigned int g_ticket;

static __device__ __forceinline__ float warp_sum(float v) {
#pragma unroll
    for (int o = 16; o; o >>= 1) v += __shfl_xor_sync(0xFFFFFFFFu, v, o);
    return v;
}
// sum across the 4 threads of one task (lane bits 0,1)
static __device__ __forceinline__ float quad_sum(float v) {
    v += __shfl_xor_sync(0xFFFFFFFFu, v, 1);
    v += __shfl_xor_sync(0xFFFFFFFFu, v, 2);
    return v;
}

__global__ __launch_bounds__(THREADS, 7) void proj_loss(
    const float* __restrict__ Kmat,   // (B,V,3,3)
    const float* __restrict__ cam,    // (B,V,3,4)
    const float* __restrict__ kw,     // (B,J,3)
    const float* __restrict__ ik,     // (B,V,J,2)
    float* __restrict__ out)
{
    extern __shared__ float sm[];
    float4* sm4 = (float4*)sm;
    __shared__ float s_w[4];
    __shared__ int s_last;

    const int tid = threadIdx.x;
    const int b0 = blockIdx.x * BPB;

    // ---------------- staging: ALL gmem loads dense warp-coalesced ----------------
    {   // kw: 8*24 = 192 f4
        const float4* g = (const float4*)(kw + (size_t)b0 * 96);
#pragma unroll
        for (int r = 0; r < 2; ++r) {
            int i = tid + r * 128;
            if (i < 192) {
                int b = i / 24, k = i - b * 24;
                sm4[KW4 + b * 25 + k] = __ldcs(&g[i]);
            }
        }
    }
    {   // ik: 8*4*16 = 512 f4, dense LDG.128 -> transposed [slot s][owner thread]
        const float4* g = (const float4*)(ik + (size_t)b0 * 256);
#pragma unroll
        for (int r = 0; r < 4; ++r) {
            int i = tid + r * 128;
            int task = i >> 4, p = i & 15;      // p = f4 position within task
            int hh = p >> 2, s = p & 3;         // owner quarter, slot
            sm4[IK4 + s * 129 + task * 4 + hh] = __ldcs(&g[i]);
        }
    }
    {   // cam: 8*12 = 96 f4 -> scalar scatter to odd-stride rows
        const float4* g = (const float4*)(cam + (size_t)b0 * 48);
        if (tid < 96) {
            int b = tid / 12, k = tid - b * 12;
            float4 val = __ldcs(&g[tid]);
            int base = CAMF + b * 49 + k * 4;
            sm[base] = val.x; sm[base + 1] = val.y;
            sm[base + 2] = val.z; sm[base + 3] = val.w;
        }
    }
    {   // K: 8*9 = 72 f4
        const float4* g = (const float4*)(Kmat + (size_t)b0 * 36);
        if (tid < 72) {
            int b = tid / 9, k = tid - b * 9;
            float4 val = __ldcs(&g[tid]);
            int base = KKF + b * 37 + k * 4;
            sm[base] = val.x; sm[base + 1] = val.y;
            sm[base + 2] = val.z; sm[base + 3] = val.w;
        }
    }
    __syncthreads();

    // ------------- mapping: task (bl, v), quarter h -> joints 8h..8h+7 -------------
    const int h  = tid & 3;
    const int v  = (tid >> 2) & 3;
    const int bl = tid >> 4;

    // ik quarter: 4 conflict-free lane-consecutive LDS.128, cached in regs
    float4 q[4];
#pragma unroll
    for (int k = 0; k < 4; ++k) q[k] = sm4[IK4 + k * 129 + tid];
    float ni2 = 0.f;
#pragma unroll
    for (int k = 0; k < 4; ++k) {
        ni2 = fmaf(q[k].x, q[k].x, fmaf(q[k].y, q[k].y, ni2));
        ni2 = fmaf(q[k].z, q[k].z, fmaf(q[k].w, q[k].w, ni2));
    }

    // camera / intrinsics (smem broadcast reads)
    const float* cv = &sm[CAMF + bl * 49 + v * 12];
    const float R00=cv[0], R01=cv[1], R02=cv[2],  t0=cv[3];
    const float R10=cv[4], R11=cv[5], R12=cv[6],  t1=cv[7];
    const float R20=cv[8], R21=cv[9], R22=cv[10], t2=cv[11];
    const float* kp = &sm[KKF + bl * 37 + v * 9];
    const float K00=kp[0], K01=kp[1], c0=kp[2];
    const float K10=kp[3], K11=kp[4], c1=kp[5];

    // folded rows: ux = (A0.X + d0)*izb + c0
    const float A00 = fmaf(K00, R00, K01 * R10);
    const float A01 = fmaf(K00, R01, K01 * R11);
    const float A02 = fmaf(K00, R02, K01 * R12);
    const float d0  = fmaf(K00, t0,  K01 * t1);
    const float A10 = fmaf(K10, R00, K11 * R10);
    const float A11 = fmaf(K10, R01, K11 * R11);
    const float A12 = fmaf(K10, R02, K11 * R12);
    const float d1  = fmaf(K10, t0,  K11 * t1);

    // single pass over X: numerators + z partial
    const int xb = KW4 + bl * 25 + 6 * h;
    float2 uv[8];
    float Szp = 0.f;
#pragma unroll
    for (int g = 0; g < 2; ++g) {
        float4 p0 = sm4[xb + g * 3];
        float4 p1 = sm4[xb + g * 3 + 1];
        float4 p2 = sm4[xb + g * 3 + 2];
        float xs[4] = {p0.x, p0.w, p1.z, p2.y};
        float ys[4] = {p0.y, p1.x, p1.w, p2.z};
        float zs[4] = {p0.z, p1.y, p2.x, p2.w};
#pragma unroll
        for (int j = 0; j < 4; ++j) {
            int jj = g * 4 + j;
            uv[jj].x = fmaf(A00, xs[j], fmaf(A01, ys[j], fmaf(A02, zs[j], d0)));
            uv[jj].y = fmaf(A10, xs[j], fmaf(A11, ys[j], fmaf(A12, zs[j], d1)));
            Szp = fmaf(R20, xs[j], fmaf(R21, ys[j], fmaf(R22, zs[j], Szp)));
        }
    }
    const float zbar = quad_sum(Szp) * (1.0f / 32.0f) + t2;
    const float izb  = __fdividef(1.0f, zbar);

    // finish uv, accumulate norms (registers only)
    float np2 = 0.f;
#pragma unroll
    for (int j = 0; j < 8; ++j) {
        float ux = fmaf(uv[j].x, izb, c0);
        float uy = fmaf(uv[j].y, izb, c1);
        uv[j] = make_float2(ux, uy);
        np2 = fmaf(ux, ux, fmaf(uy, uy, np2));
    }
    np2 = quad_sum(np2);
    ni2 = quad_sum(ni2);
    const float rp = rsqrtf(np2);
    const float ri = rsqrtf(ni2);

    float acc = 0.f;
#pragma unroll
    for (int k = 0; k < 4; ++k) {
        acc += fabsf(fmaf(uv[2*k].x,   rp, -q[k].x * ri))
             + fabsf(fmaf(uv[2*k].y,   rp, -q[k].y * ri))
             + fabsf(fmaf(uv[2*k+1].x, rp, -q[k].z * ri))
             + fabsf(fmaf(uv[2*k+1].y, rp, -q[k].w * ri));
    }

    // ---------------- block partial + last-block deterministic reduce --------
    acc = warp_sum(acc);
    if ((tid & 31) == 0) s_w[tid >> 5] = acc;
    __syncthreads();
    if (tid == 0) {
        float bsum = s_w[0] + s_w[1] + s_w[2] + s_w[3];
        __stcg(&g_partials[blockIdx.x], bsum);
        __threadfence();
        unsigned int t = atomicAdd(&g_ticket, 1u);
        s_last = (t == NBLK - 1u);
    }
    __syncthreads();

    if (s_last) {
        float a = 0.f;
#pragma unroll
        for (int i = 0; i < NBLK / THREADS; ++i)
            a += __ldcg(&g_partials[tid * (NBLK / THREADS) + i]);
        a = warp_sum(a);
        if ((tid & 31) == 0) s_w[tid >> 5] = a;
        __syncthreads();
        if (tid == 0) {
            float tot = s_w[0] + s_w[1] + s_w[2] + s_w[3];
            out[0] = tot * (1.0f / (64.0f * (float)BB * (float)VV));
            g_ticket = 0u;
        }
    }
}

extern "C" void kernel_launch(void* const* d_in, const int* in_sizes, int n_in,
                              void* d_out, int out_size)
{
    const float* Kmat = (const float*)d_in[0];  // (B,V,3,3)
    const float* cam  = (const float*)d_in[1];  // (B,V,3,4)
    const float* kw   = (const float*)d_in[2];  // (B,J,3)
    const float* ik   = (const float*)d_in[3];  // (B,V,J,2)
    float* out = (float*)d_out;

    cudaFuncSetAttribute(proj_loss, cudaFuncAttributeMaxDynamicSharedMemorySize, SMEM_BYTES);
    proj_loss<<<NBLK, THREADS, SMEM_BYTES>>>(Kmat, cam, kw, ik, out);
}

// round 8
// speedup vs baseline: 1.2538x; 1.2456x over previous
#include <cuda_runtime.h>

#define BB 65536
#define VV 4
#define BPB 16                        // batches per block
#define THREADS 128                   // 2 threads per (batch,view) task
#define NBLK (BB / BPB)               // 4096

// shared layout, f4 units unless noted
#define KW4   0                       // 16 batches x stride 25 f4 (24 data + 1 pad)
#define IK4   400                     // transposed: 8 slots x stride 129 f4
#define CAMF  5728                    // floats: 16 x stride 49 (48 data + 1 pad)
#define KKF   6512                    // floats: 16 x stride 37 (36 data + 1 pad)
#define SMEM_FLOATS 7104
#define SMEM_BYTES (SMEM_FLOATS * 4)  // 28416

__device__ float g_partials[NBLK];
__device__ unsigned int g_ticket;

static __device__ __forceinline__ float warp_sum(float v) {
#pragma unroll
    for (int o = 16; o; o >>= 1) v += __shfl_xor_sync(0xFFFFFFFFu, v, o);
    return v;
}

__global__ __launch_bounds__(THREADS, 5) void proj_loss(
    const float* __restrict__ Kmat,   // (B,V,3,3)
    const float* __restrict__ cam,    // (B,V,3,4)
    const float* __restrict__ kw,     // (B,J,3)
    const float* __restrict__ ik,     // (B,V,J,2)
    float* __restrict__ out)
{
    extern __shared__ float sm[];
    float4* sm4 = (float4*)sm;
    __shared__ float s_w[4];
    __shared__ int s_last;

    const int tid = threadIdx.x;
    const int b0 = blockIdx.x * BPB;

    // ---------------- staging (identical to R5: proven layout) ----------------
    {   // kw: 16*24 = 384 f4
        const float4* g = (const float4*)(kw + (size_t)b0 * 96);
#pragma unroll
        for (int r = 0; r < 3; ++r) {
            int i = tid + r * 128, b = i / 24, k = i - b * 24;
            sm4[KW4 + b * 25 + k] = __ldcs(&g[i]);
        }
    }
    {   // ik: 1024 f4 -> transposed [slot s][dest-thread]
        const float4* g = (const float4*)(ik + (size_t)b0 * 256);
#pragma unroll
        for (int r = 0; r < 8; ++r) {
            int i = tid + r * 128;
            int task = i >> 4, rem = i & 15;
            int hh = rem >> 3, s = rem & 7;
            sm4[IK4 + s * 129 + 2 * task + hh] = __ldcs(&g[i]);
        }
    }
    {   // cam: 192 f4 -> scalar scatter, odd stride
        const float4* g = (const float4*)(cam + (size_t)b0 * 48);
#pragma unroll
        for (int r = 0; r < 2; ++r) {
            int i = tid + r * 128;
            if (i < 192) {
                int b = i / 12, k = i - b * 12;
                float4 val = __ldcs(&g[i]);
                int base = CAMF + b * 49 + k * 4;
                sm[base] = val.x; sm[base + 1] = val.y;
                sm[base + 2] = val.z; sm[base + 3] = val.w;
            }
        }
    }
    {   // K: 144 f4
        const float4* g = (const float4*)(Kmat + (size_t)b0 * 36);
#pragma unroll
        for (int r = 0; r < 2; ++r) {
            int i = tid + r * 128;
            if (i < 144) {
                int b = i / 9, k = i - b * 9;
                float4 val = __ldcs(&g[i]);
                int base = KKF + b * 37 + k * 4;
                sm[base] = val.x; sm[base + 1] = val.y;
                sm[base + 2] = val.z; sm[base + 3] = val.w;
            }
        }
    }
    __syncthreads();

    // ------------- mapping: 2 threads per task, 16 joints each -------------
    const int h  = tid & 1;           // half (joints 16h .. 16h+15)
    const int v  = (tid >> 1) & 3;    // view
    const int bl = tid >> 3;          // local batch

    const float* cv = &sm[CAMF + bl * 49 + v * 12];
    const float R00=cv[0], R01=cv[1], R02=cv[2],  t0=cv[3];
    const float R10=cv[4], R11=cv[5], R12=cv[6],  t1=cv[7];
    const float R20=cv[8], R21=cv[9], R22=cv[10], t2=cv[11];
    const float* kp = &sm[KKF + bl * 37 + v * 9];
    const float K00=kp[0], K01=kp[1], c0=kp[2];
    const float K10=kp[3], K11=kp[4], c1=kp[5];

    // folded rows: ux = (A0.X + d0)*izb + c0
    const float A00 = fmaf(K00, R00, K01 * R10);
    const float A01 = fmaf(K00, R01, K01 * R11);
    const float A02 = fmaf(K00, R02, K01 * R12);
    const float d0  = fmaf(K00, t0,  K01 * t1);
    const float A10 = fmaf(K10, R00, K11 * R10);
    const float A11 = fmaf(K10, R01, K11 * R11);
    const float A12 = fmaf(K10, R02, K11 * R12);
    const float d1  = fmaf(K10, t0,  K11 * t1);

    // ---------- single pass over X: uv numerators (regs) + z partial ----------
    const int xb = KW4 + bl * 25 + 12 * h;   // this half's 12 f4 of X
    float2 uv[16];
    float Szp = 0.f;
#pragma unroll
    for (int g = 0; g < 4; ++g) {
        float4 p0 = sm4[xb + g * 3];
        float4 p1 = sm4[xb + g * 3 + 1];
        float4 p2 = sm4[xb + g * 3 + 2];
        float xs[4] = {p0.x, p0.w, p1.z, p2.y};
        float ys[4] = {p0.y, p1.x, p1.w, p2.z};
        float zs[4] = {p0.z, p1.y, p2.x, p2.w};
#pragma unroll
        for (int j = 0; j < 4; ++j) {
            int jj = g * 4 + j;
            uv[jj].x = fmaf(A00, xs[j], fmaf(A01, ys[j], fmaf(A02, zs[j], d0)));
            uv[jj].y = fmaf(A10, xs[j], fmaf(A11, ys[j], fmaf(A12, zs[j], d1)));
            Szp = fmaf(R20, xs[j], fmaf(R21, ys[j], fmaf(R22, zs[j], Szp)));
        }
    }
    Szp += __shfl_xor_sync(0xFFFFFFFFu, Szp, 1);
    const float zbar = Szp * (1.0f / 32.0f) + t2;
    const float izb  = __fdividef(1.0f, zbar);

    // ---------- ni2 from transposed ik (conflict-free LDS.128) ----------
    float ni2 = 0.f;
#pragma unroll
    for (int s = 0; s < 8; ++s) {
        float4 q = sm4[IK4 + s * 129 + tid];
        ni2 = fmaf(q.x, q.x, fmaf(q.y, q.y, ni2));
        ni2 = fmaf(q.z, q.z, fmaf(q.w, q.w, ni2));
    }

    // finish uv in regs, accumulate np2
    float np2 = 0.f;
#pragma unroll
    for (int j = 0; j < 16; ++j) {
        float ux = fmaf(uv[j].x, izb, c0);
        float uy = fmaf(uv[j].y, izb, c1);
        uv[j] = make_float2(ux, uy);
        np2 = fmaf(ux, ux, fmaf(uy, uy, np2));
    }
    np2 += __shfl_xor_sync(0xFFFFFFFFu, np2, 1);
    ni2 += __shfl_xor_sync(0xFFFFFFFFu, ni2, 1);
    const float rp = rsqrtf(np2);
    const float ri = rsqrtf(ni2);

    // ---------- pass C: re-read ik, L1 of scale-free difference ----------
    float acc = 0.f;
#pragma unroll
    for (int s = 0; s < 8; ++s) {
        float4 q = sm4[IK4 + s * 129 + tid];
        acc += fabsf(fmaf(uv[2*s].x,   rp, -q.x * ri))
             + fabsf(fmaf(uv[2*s].y,   rp, -q.y * ri))
             + fabsf(fmaf(uv[2*s+1].x, rp, -q.z * ri))
             + fabsf(fmaf(uv[2*s+1].y, rp, -q.w * ri));
    }

    // ---------------- block partial + last-block deterministic reduce --------
    acc = warp_sum(acc);
    if ((tid & 31) == 0) s_w[tid >> 5] = acc;
    __syncthreads();
    if (tid == 0) {
        float bsum = s_w[0] + s_w[1] + s_w[2] + s_w[3];
        __stcg(&g_partials[blockIdx.x], bsum);
        __threadfence();
        unsigned int t = atomicAdd(&g_ticket, 1u);
        s_last = (t == NBLK - 1u);
    }
    __syncthreads();

    if (s_last) {
        float a = 0.f;
#pragma unroll
        for (int i = 0; i < NBLK / THREADS; ++i)
            a += __ldcg(&g_partials[tid * (NBLK / THREADS) + i]);
        a = warp_sum(a);
        if ((tid & 31) == 0) s_w[tid >> 5] = a;
        __syncthreads();
        if (tid == 0) {
            float tot = s_w[0] + s_w[1] + s_w[2] + s_w[3];
            out[0] = tot * (1.0f / (64.0f * (float)BB * (float)VV));
            g_ticket = 0u;
        }
    }
}

extern "C" void kernel_launch(void* const* d_in, const int* in_sizes, int n_in,
                              void* d_out, int out_size)
{
    const float* Kmat = (const float*)d_in[0];  // (B,V,3,3)
    const float* cam  = (const float*)d_in[1];  // (B,V,3,4)
    const float* kw   = (const float*)d_in[2];  // (B,J,3)
    const float* ik   = (const float*)d_in[3];  // (B,V,J,2)
    float* out = (float*)d_out;

    cudaFuncSetAttribute(proj_loss, cudaFuncAttributeMaxDynamicSharedMemorySize, SMEM_BYTES);
    proj_loss<<<NBLK, THREADS, SMEM_BYTES>>>(Kmat, cam, kw, ik, out);
}